// round 12
// baseline (speedup 1.0000x reference)
#include <cuda_runtime.h>
#include <cuda_bf16.h>

#define NN    64
#define CC    128
#define HWP   3136
#define MTOT  200704
#define EPSI  1e-5f
#define TITER 10
#define NSB   128
#define GCHUNK 784
#define GBLK  256

// gram smem: [buf 0/1][128 rows][48B] (hi only, 1-pass)
#define PITCHB 48
#define GBUF   (128 * PITCHB)

// whit smem layout (bytes, dynamic)
#define WPITCH 272
#define XPITCH 144
#define S_WH   0
#define S_WL   (128*WPITCH)
#define S_XH   (2*128*WPITCH)
#define S_XL   (S_XH + 128*XPITCH)
#define S_BIAS (S_XL + 128*XPITCH)
#define WHIT_SMEM (S_BIAS + 128*4)

// ---------------- scratch ----------------
__device__ float d_gpart[GBLK * CC * CC];
__device__ float d_cpart[GBLK * CC];
__device__ float d_gram[CC * CC];
__device__ float d_chsum[CC];
__device__ float d_Sig[CC * CC];
__device__ float d_P2[2][CC * CC];
__device__ __nv_bfloat16 d_wmh[CC * CC];
__device__ __nv_bfloat16 d_wml[CC * CC];
__device__ float d_bias2[CC];
__device__ float d_trace;
__device__ unsigned g_bar;

// ---------------- helpers ----------------
__device__ __forceinline__ unsigned smem_u32(const void* p) {
    unsigned r; asm("{ .reg .u64 t; cvta.to.shared.u64 t, %1; cvt.u32.u64 %0, t; }" : "=r"(r) : "l"(p)); return r;
}
__device__ __forceinline__ void ldsm_x4(unsigned &r0, unsigned &r1, unsigned &r2, unsigned &r3, unsigned a) {
    asm volatile("ldmatrix.sync.aligned.m8n8.x4.shared.b16 {%0,%1,%2,%3}, [%4];"
                 : "=r"(r0), "=r"(r1), "=r"(r2), "=r"(r3) : "r"(a));
}
__device__ __forceinline__ void ldsm_x2t(unsigned &r0, unsigned &r1, unsigned a) {
    asm volatile("ldmatrix.sync.aligned.m8n8.x2.trans.shared.b16 {%0,%1}, [%2];"
                 : "=r"(r0), "=r"(r1) : "r"(a));
}
__device__ __forceinline__ void mma_bf16(float* d, unsigned a0, unsigned a1, unsigned a2, unsigned a3,
                                         unsigned b0, unsigned b1) {
    asm volatile("mma.sync.aligned.m16n8k16.row.col.f32.bf16.bf16.f32 "
                 "{%0,%1,%2,%3}, {%4,%5,%6,%7}, {%8,%9}, {%0,%1,%2,%3};"
                 : "+f"(d[0]), "+f"(d[1]), "+f"(d[2]), "+f"(d[3])
                 : "r"(a0), "r"(a1), "r"(a2), "r"(a3), "r"(b0), "r"(b1));
}
__device__ __forceinline__ unsigned pkbf(float a, float b) {
    __nv_bfloat162 t(__float2bfloat16(a), __float2bfloat16(b));
    return *(unsigned*)&t;
}

// ---------------- kernel 1: Gram via mma.sync, 1-pass bf16, UPPER-TRIANGLE ONLY ----
// Warp w (rows 16w..16w+15) computes only 16-col pairs p >= w (block upper triangle).
// Mirror is filled in reduce_kernel; accumulation order identical -> exact symmetry.
__global__ void __launch_bounds__(256, 2) gram_kernel(const float* __restrict__ X) {
    __shared__ __align__(16) char sm[2 * GBUF];
    __shared__ float chs[CC];
    const int tid = threadIdx.x, wid = tid >> 5, lane = tid & 31;
    const unsigned smb = smem_u32(sm);
    const int n = blockIdx.x >> 2;
    const int pbase = (blockIdx.x & 3) * GCHUNK;
    const float* Xn = X + (size_t)n * (CC * HWP) + pbase;

    const int r = tid >> 1, q = tid & 1;
    const float* gsrc = Xn + (size_t)r * HWP + q * 8;
    if (tid < CC) chs[tid] = 0.f;

    float acc[16][4];
#pragma unroll
    for (int j = 0; j < 16; ++j)
#pragma unroll
        for (int z = 0; z < 4; ++z) acc[j][z] = 0.f;
    float cs = 0.f;

    const unsigned a_off = (unsigned)((wid * 16 + (lane & 15)) * PITCHB + (lane >> 4) * 16);
    const unsigned b_row = (unsigned)((lane >> 4) * 8 + (lane & 7));
    const unsigned b_koff = (unsigned)(((lane >> 3) & 1) * 16);
    const unsigned st_off = (unsigned)(r * PITCHB + q * 16);

    float4 pv0 = *(const float4*)(gsrc);
    float4 pv1 = *(const float4*)(gsrc + 4);

    for (int t = 0; t < 49; ++t) {
        char* base = sm + (t & 1) * GBUF;
        {
            unsigned h0 = pkbf(pv0.x, pv0.y), h1 = pkbf(pv0.z, pv0.w);
            unsigned h2 = pkbf(pv1.x, pv1.y), h3 = pkbf(pv1.z, pv1.w);
            *(uint4*)(base + st_off) = make_uint4(h0, h1, h2, h3);
            cs += ((pv0.x + pv0.y) + (pv0.z + pv0.w)) + ((pv1.x + pv1.y) + (pv1.z + pv1.w));
        }
        __syncthreads();
        if (t < 48) {
            pv0 = *(const float4*)(gsrc + (t + 1) * 16);
            pv1 = *(const float4*)(gsrc + (t + 1) * 16 + 4);
        }
        const unsigned tb = smb + (unsigned)((t & 1) * GBUF);
        unsigned ah0, ah1, ah2, ah3;
        ldsm_x4(ah0, ah1, ah2, ah3, tb + a_off);
#pragma unroll
        for (int p = 0; p < 8; ++p) {
            if (p >= wid) {     // block upper triangle only
                const unsigned ba = tb + (unsigned)((16 * p + b_row) * PITCHB) + b_koff;
                unsigned bh0, bh1, bh2, bh3;
                ldsm_x4(bh0, bh1, bh2, bh3, ba);
                mma_bf16(acc[2*p],   ah0, ah1, ah2, ah3, bh0, bh1);
                mma_bf16(acc[2*p+1], ah0, ah1, ah2, ah3, bh2, bh3);
            }
        }
    }

    __syncthreads();
    atomicAdd(&chs[r], cs);
    __syncthreads();
    if (tid < CC) d_cpart[blockIdx.x * CC + tid] = chs[tid];

    float* gp = d_gpart + (size_t)blockIdx.x * (CC * CC);
    const int row0 = wid * 16 + (lane >> 2);
#pragma unroll
    for (int j = 0; j < 16; ++j) {
        if ((j >> 1) >= wid) {
            const int col = j * 8 + (lane & 3) * 2;
            *(float2*)(gp + row0 * CC + col)       = make_float2(acc[j][0], acc[j][1]);
            *(float2*)(gp + (row0 + 8) * CC + col) = make_float2(acc[j][2], acc[j][3]);
        }
    }
}

// ---------------- kernel 2: reduce (+ mirror lower triangle, + zero barrier/trace) ----
__global__ void reduce_kernel() {
    const int bid = blockIdx.x, tid = threadIdx.x;
    if (bid < 64) {
        const int i = bid * 256 + tid;
        const int rr = i >> 7, cc = i & 127;
        const int src = ((cc >> 4) >= (rr >> 4)) ? i : ((cc << 7) + rr);
        float s = 0.f;
#pragma unroll 8
        for (int b = 0; b < GBLK; b++) s += d_gpart[(size_t)b * (CC * CC) + src];
        d_gram[i] = s;
    } else {
        if (tid < CC) {
            float s = 0.f;
#pragma unroll 8
            for (int b = 0; b < GBLK; b++) s += d_cpart[b * CC + tid];
            d_chsum[tid] = s;
        }
        if (tid == 128) { d_trace = 0.f; g_bar = 0u; }
    }
}

// ---------------- kernel 3: Newton-Schulz, direct-L2, k-split x2 (measured-best R10) ---
__device__ __forceinline__ void gsync(unsigned &tgt) {
    __threadfence();
    __syncthreads();
    tgt += NSB;
    if (threadIdx.x == 0) {
        atomicAdd(&g_bar, 1u);
        while (*(volatile unsigned*)&g_bar < tgt) {}
    }
    __syncthreads();
}
__device__ __forceinline__ float halfdot(const float* __restrict__ v,
                                         const float* __restrict__ M, int j) {
    float a0 = 0.f, a1 = 0.f, a2 = 0.f, a3 = 0.f;
#pragma unroll
    for (int k = 0; k < 64; k += 4) {
        float4 pv = *(const float4*)(v + k);
        a0 = fmaf(pv.x, __ldcg(&M[(k + 0) * CC + j]), a0);
        a1 = fmaf(pv.y, __ldcg(&M[(k + 1) * CC + j]), a1);
        a2 = fmaf(pv.z, __ldcg(&M[(k + 2) * CC + j]), a2);
        a3 = fmaf(pv.w, __ldcg(&M[(k + 3) * CC + j]), a3);
    }
    return (a0 + a1) + (a2 + a3);
}
__global__ void __launch_bounds__(256, 1) ns_kernel(const float* __restrict__ beta) {
    __shared__ float mean_s[CC], pr_s[CC], t1_s[CC], t2_s[CC];
    __shared__ float p1[2][CC], p2[2][CC], pu[2][CC];
    __shared__ float rtr_s;
    const int tid = threadIdx.x;
    const int j = tid & 127, h = tid >> 7;
    const int r = blockIdx.x;

    if (h == 0) mean_s[j] = d_chsum[j] * (1.f / (float)MTOT);
    __syncthreads();
    if (h == 0) {
        float sig = d_gram[r*CC + j] * (1.f / (float)MTOT) - mean_s[r] * mean_s[j]
                    + ((j == r) ? EPSI : 0.f);
        __stcg(&d_Sig[r*CC + j], sig);
        __stcg(&d_P2[0][r*CC + j], (j == r) ? 1.f : 0.f);
        if (j == r) atomicAdd(&d_trace, sig);
    }
    unsigned tgt = 0;
    gsync(tgt);
    if (tid == 0) rtr_s = 1.f / *(volatile float*)&d_trace;
    __syncthreads();
    const float rtr = rtr_s;

    int cur = 0;
    for (int it = 0; it < TITER; ++it) {
        const float* P = d_P2[cur];
        if (h == 0) pr_s[j] = __ldcg(&P[r*CC + j]);
        __syncthreads();
        p1[h][j] = halfdot(pr_s + h*64, P + (size_t)h*64*CC, j);
        __syncthreads();
        if (h == 0) t1_s[j] = p1[0][j] + p1[1][j];
        __syncthreads();
        p2[h][j] = halfdot(t1_s + h*64, P + (size_t)h*64*CC, j);
        __syncthreads();
        if (h == 0) t2_s[j] = p2[0][j] + p2[1][j];
        __syncthreads();
        pu[h][j] = halfdot(t2_s + h*64, d_Sig + (size_t)h*64*CC, j);
        __syncthreads();
        if (h == 0) {
            float u = pu[0][j] + pu[1][j];
            __stcg(&d_P2[1 - cur][r*CC + j], 1.5f * pr_s[j] - 0.5f * rtr * u);
        }
        gsync(tgt);
        cur ^= 1;
    }

    if (h == 0) {
        float w = __ldcg(&d_P2[cur][r*CC + j]) * sqrtf(rtr);
        __nv_bfloat16 wh = __float2bfloat16(w);
        float whf = __bfloat162float(wh);
        __nv_bfloat16 wl = __float2bfloat16(w - whf);
        d_wmh[r*CC + j] = wh;
        d_wml[r*CC + j] = wl;
        float wq = whf + __bfloat162float(wl);
        t1_s[j] = wq * mean_s[j];
    }
    __syncthreads();
    for (int s = 64; s > 0; s >>= 1) {
        if (tid < s) t1_s[tid] += t1_s[tid + s];
        __syncthreads();
    }
    if (tid == 0) d_bias2[r] = beta[r] - t1_s[0];
}

// ---------------- kernel 4: whitening, 4 p-tiles + register prefetch pipeline ----
__global__ void __launch_bounds__(256) whit_kernel(const float* __restrict__ X,
                                                   float* __restrict__ Y) {
    extern __shared__ char sm[];
    const int tid = threadIdx.x, wid = tid >> 5, lane = tid & 31;
    const unsigned smb = smem_u32(sm);

    {   // stage wm hi/lo once per CTA
        const unsigned* wh = (const unsigned*)d_wmh;
        const unsigned* wl = (const unsigned*)d_wml;
#pragma unroll 8
        for (int i = tid; i < 8192; i += 256) {
            int c = i >> 6, dp = i & 63;
            unsigned off = (unsigned)(c * WPITCH + dp * 4);
            *(unsigned*)(sm + S_WH + off) = wh[i];
            *(unsigned*)(sm + S_WL + off) = wl[i];
        }
    }
    if (tid < 128) ((float*)(sm + S_BIAS))[tid] = d_bias2[tid];

    const unsigned arow = (unsigned)(wid * 16 + (lane & 15));
    const unsigned acol = (unsigned)((lane >> 4) * 16);
    const unsigned brln = (unsigned)(lane & 15);
    const int cr = tid >> 2, cq = tid & 3;

    // prefetch tile 0
    float4 pf[8];
    {
        const int g0 = blockIdx.x * 4;
        const int n0 = g0 / 49, pp0 = (g0 % 49) * 64;
#pragma unroll
        for (int hh = 0; hh < 2; ++hh) {
            const float* xp = X + ((size_t)n0 * CC + cr + hh * 64) * HWP + pp0 + cq * 16;
#pragma unroll
            for (int i = 0; i < 4; ++i) pf[hh * 4 + i] = *(const float4*)(xp + 4 * i);
        }
    }

    for (int t = 0; t < 4; ++t) {
        const int g = blockIdx.x * 4 + t;
        const int n = g / 49, p0 = (g % 49) * 64;
        if (t) __syncthreads();
        {   // convert prefetched regs -> smem bf16 hi/lo
#pragma unroll
            for (int hh = 0; hh < 2; ++hh) {
                const int row = cr + hh * 64;
                unsigned hi[8], lo[8];
#pragma unroll
                for (int i = 0; i < 4; ++i) {
                    float4 v = pf[hh * 4 + i];
                    __nv_bfloat16 hx = __float2bfloat16(v.x), hy = __float2bfloat16(v.y);
                    __nv_bfloat16 hz = __float2bfloat16(v.z), hw = __float2bfloat16(v.w);
                    __nv_bfloat162 hp0(hx, hy), hp1(hz, hw);
                    hi[2*i]   = *(unsigned*)&hp0;
                    hi[2*i+1] = *(unsigned*)&hp1;
                    lo[2*i]   = pkbf(v.x - __bfloat162float(hx), v.y - __bfloat162float(hy));
                    lo[2*i+1] = pkbf(v.z - __bfloat162float(hz), v.w - __bfloat162float(hw));
                }
                const unsigned off = (unsigned)(row * XPITCH + cq * 32);
                *(uint4*)(sm + S_XH + off)      = make_uint4(hi[0], hi[1], hi[2], hi[3]);
                *(uint4*)(sm + S_XH + off + 16) = make_uint4(hi[4], hi[5], hi[6], hi[7]);
                *(uint4*)(sm + S_XL + off)      = make_uint4(lo[0], lo[1], lo[2], lo[3]);
                *(uint4*)(sm + S_XL + off + 16) = make_uint4(lo[4], lo[5], lo[6], lo[7]);
            }
        }
        __syncthreads();

        if (t < 3) {   // prefetch tile t+1 (lands during MMA below)
            const int g2 = blockIdx.x * 4 + t + 1;
            const int n2 = g2 / 49, pp2 = (g2 % 49) * 64;
#pragma unroll
            for (int hh = 0; hh < 2; ++hh) {
                const float* xp = X + ((size_t)n2 * CC + cr + hh * 64) * HWP + pp2 + cq * 16;
#pragma unroll
                for (int i = 0; i < 4; ++i) pf[hh * 4 + i] = *(const float4*)(xp + 4 * i);
            }
        }

        float acc[8][4];
#pragma unroll
        for (int jj = 0; jj < 8; ++jj)
#pragma unroll
            for (int z = 0; z < 4; ++z) acc[jj][z] = 0.f;

#pragma unroll
        for (int kt = 0; kt < 8; ++kt) {
            const int k0 = kt * 16;
            unsigned aaddr = smb + S_WH + arow * WPITCH + (unsigned)(k0 * 2) + acol;
            unsigned ah0, ah1, ah2, ah3, al0, al1, al2, al3;
            ldsm_x4(ah0, ah1, ah2, ah3, aaddr);
            ldsm_x4(al0, al1, al2, al3, aaddr + (S_WL - S_WH));
            const unsigned bbase = smb + S_XH + (unsigned)((k0 + brln) * XPITCH);
#pragma unroll
            for (int jj = 0; jj < 8; ++jj) {
                unsigned bh0, bh1, bl0, bl1;
                ldsm_x2t(bh0, bh1, bbase + jj * 16);
                ldsm_x2t(bl0, bl1, bbase + jj * 16 + (S_XL - S_XH));
                mma_bf16(acc[jj], ah0, ah1, ah2, ah3, bh0, bh1);
                mma_bf16(acc[jj], ah0, ah1, ah2, ah3, bl0, bl1);
                mma_bf16(acc[jj], al0, al1, al2, al3, bh0, bh1);
            }
        }

        const int row0 = wid * 16 + (lane >> 2);
        const float b0 = ((const float*)(sm + S_BIAS))[row0];
        const float b1 = ((const float*)(sm + S_BIAS))[row0 + 8];
        float* y0 = Y + ((size_t)n * CC + row0) * HWP + p0 + (lane & 3) * 2;
#pragma unroll
        for (int jj = 0; jj < 8; ++jj) {
            *(float2*)(y0 + 8 * jj)           = make_float2(acc[jj][0] + b0, acc[jj][1] + b0);
            *(float2*)(y0 + 8 * jj + 8 * HWP) = make_float2(acc[jj][2] + b1, acc[jj][3] + b1);
        }
    }
}

// ---------------- launch ----------------
extern "C" void kernel_launch(void* const* d_in, const int* in_sizes, int n_in,
                              void* d_out, int out_size) {
    const float* X = (const float*)d_in[0];
    const float* beta = (const float*)d_in[1];
    float* Y = (float*)d_out;
    cudaFuncSetAttribute(whit_kernel, cudaFuncAttributeMaxDynamicSharedMemorySize, WHIT_SMEM);
    gram_kernel<<<GBLK, 256>>>(X);
    reduce_kernel<<<65, 256>>>();
    ns_kernel<<<NSB, 256>>>(beta);
    whit_kernel<<<784, 256, WHIT_SMEM>>>(X, Y);
}

// round 13
// speedup vs baseline: 1.0926x; 1.0926x over previous
#include <cuda_runtime.h>
#include <cuda_bf16.h>

#define NN    64
#define CC    128
#define HWP   3136
#define MTOT  200704
#define EPSI  1e-5f
#define TITER 10
#define NSB   128
#define GCHUNK 784
#define GBLK  256

// gram smem: [buf 0/1][128 rows][48B] (hi only, 1-pass)
#define PITCHB 48
#define GBUF   (128 * PITCHB)

// whit smem (tf32 single-pass): wm [c][d] pitch 132 floats, X [d][p] pitch 72 floats
#define WP 132
#define XP 72
#define S_W    0
#define S_X    (128 * WP * 4)            // 67584
#define S_BIAS (S_X + 128 * XP * 4)      // 104448
#define WHIT_SMEM (S_BIAS + 512)         // 104960

// ---------------- scratch ----------------
__device__ float d_gpart[GBLK * CC * CC];
__device__ float d_cpart[GBLK * CC];
__device__ float d_gram[CC * CC];
__device__ float d_chsum[CC];
__device__ float d_Sig[CC * CC];
__device__ float d_P2[2][CC * CC];
__device__ float d_wmf[CC * CC];          // wm fp32, row-major [c][d]
__device__ float d_bias2[CC];
__device__ float d_trace;
__device__ unsigned g_bar;

// ---------------- helpers ----------------
__device__ __forceinline__ unsigned smem_u32(const void* p) {
    unsigned r; asm("{ .reg .u64 t; cvta.to.shared.u64 t, %1; cvt.u32.u64 %0, t; }" : "=r"(r) : "l"(p)); return r;
}
__device__ __forceinline__ void ldsm_x4(unsigned &r0, unsigned &r1, unsigned &r2, unsigned &r3, unsigned a) {
    asm volatile("ldmatrix.sync.aligned.m8n8.x4.shared.b16 {%0,%1,%2,%3}, [%4];"
                 : "=r"(r0), "=r"(r1), "=r"(r2), "=r"(r3) : "r"(a));
}
__device__ __forceinline__ void mma_bf16(float* d, unsigned a0, unsigned a1, unsigned a2, unsigned a3,
                                         unsigned b0, unsigned b1) {
    asm volatile("mma.sync.aligned.m16n8k16.row.col.f32.bf16.bf16.f32 "
                 "{%0,%1,%2,%3}, {%4,%5,%6,%7}, {%8,%9}, {%0,%1,%2,%3};"
                 : "+f"(d[0]), "+f"(d[1]), "+f"(d[2]), "+f"(d[3])
                 : "r"(a0), "r"(a1), "r"(a2), "r"(a3), "r"(b0), "r"(b1));
}
__device__ __forceinline__ void mma_tf32(float* d, unsigned a0, unsigned a1, unsigned a2, unsigned a3,
                                         unsigned b0, unsigned b1) {
    asm volatile("mma.sync.aligned.m16n8k8.row.col.f32.tf32.tf32.f32 "
                 "{%0,%1,%2,%3}, {%4,%5,%6,%7}, {%8,%9}, {%0,%1,%2,%3};"
                 : "+f"(d[0]), "+f"(d[1]), "+f"(d[2]), "+f"(d[3])
                 : "r"(a0), "r"(a1), "r"(a2), "r"(a3), "r"(b0), "r"(b1));
}
__device__ __forceinline__ unsigned pkbf(float a, float b) {
    __nv_bfloat162 t(__float2bfloat16(a), __float2bfloat16(b));
    return *(unsigned*)&t;
}
__device__ __forceinline__ unsigned cvt_tf32(float f) {
    unsigned r; asm("cvt.rna.tf32.f32 %0, %1;" : "=r"(r) : "f"(f)); return r;
}

// ---------------- kernel 1: Gram via mma.sync, 1-pass bf16 (R10 measured-good) ----
__global__ void __launch_bounds__(256, 2) gram_kernel(const float* __restrict__ X) {
    __shared__ __align__(16) char sm[2 * GBUF];
    __shared__ float chs[CC];
    const int tid = threadIdx.x, wid = tid >> 5, lane = tid & 31;
    const unsigned smb = smem_u32(sm);
    const int n = blockIdx.x >> 2;
    const int pbase = (blockIdx.x & 3) * GCHUNK;
    const float* Xn = X + (size_t)n * (CC * HWP) + pbase;

    const int r = tid >> 1, q = tid & 1;
    const float* gsrc = Xn + (size_t)r * HWP + q * 8;
    if (tid < CC) chs[tid] = 0.f;

    float acc[16][4];
#pragma unroll
    for (int j = 0; j < 16; ++j)
#pragma unroll
        for (int z = 0; z < 4; ++z) acc[j][z] = 0.f;
    float cs = 0.f;

    const unsigned a_off = (unsigned)((wid * 16 + (lane & 15)) * PITCHB + (lane >> 4) * 16);
    const unsigned b_row = (unsigned)((lane >> 4) * 8 + (lane & 7));
    const unsigned b_koff = (unsigned)(((lane >> 3) & 1) * 16);
    const unsigned st_off = (unsigned)(r * PITCHB + q * 16);

    float4 pv0 = *(const float4*)(gsrc);
    float4 pv1 = *(const float4*)(gsrc + 4);

    for (int t = 0; t < 49; ++t) {
        char* base = sm + (t & 1) * GBUF;
        {
            unsigned h0 = pkbf(pv0.x, pv0.y), h1 = pkbf(pv0.z, pv0.w);
            unsigned h2 = pkbf(pv1.x, pv1.y), h3 = pkbf(pv1.z, pv1.w);
            *(uint4*)(base + st_off) = make_uint4(h0, h1, h2, h3);
            cs += ((pv0.x + pv0.y) + (pv0.z + pv0.w)) + ((pv1.x + pv1.y) + (pv1.z + pv1.w));
        }
        __syncthreads();
        if (t < 48) {
            pv0 = *(const float4*)(gsrc + (t + 1) * 16);
            pv1 = *(const float4*)(gsrc + (t + 1) * 16 + 4);
        }
        const unsigned tb = smb + (unsigned)((t & 1) * GBUF);
        unsigned ah0, ah1, ah2, ah3;
        ldsm_x4(ah0, ah1, ah2, ah3, tb + a_off);
#pragma unroll
        for (int p = 0; p < 8; ++p) {
            const unsigned ba = tb + (unsigned)((16 * p + b_row) * PITCHB) + b_koff;
            unsigned bh0, bh1, bh2, bh3;
            ldsm_x4(bh0, bh1, bh2, bh3, ba);
            mma_bf16(acc[2*p],   ah0, ah1, ah2, ah3, bh0, bh1);
            mma_bf16(acc[2*p+1], ah0, ah1, ah2, ah3, bh2, bh3);
        }
    }

    __syncthreads();
    atomicAdd(&chs[r], cs);
    __syncthreads();
    if (tid < CC) d_cpart[blockIdx.x * CC + tid] = chs[tid];

    float* gp = d_gpart + (size_t)blockIdx.x * (CC * CC);
    const int row0 = wid * 16 + (lane >> 2);
#pragma unroll
    for (int j = 0; j < 16; ++j) {
        const int col = j * 8 + (lane & 3) * 2;
        *(float2*)(gp + row0 * CC + col)       = make_float2(acc[j][0], acc[j][1]);
        *(float2*)(gp + (row0 + 8) * CC + col) = make_float2(acc[j][2], acc[j][3]);
    }
}

// ---------------- kernel 2: reduce (plain coalesced) + zero barrier/trace ----------------
__global__ void reduce_kernel() {
    const int bid = blockIdx.x, tid = threadIdx.x;
    if (bid < 64) {
        const int i = bid * 256 + tid;
        float s = 0.f;
#pragma unroll 8
        for (int b = 0; b < GBLK; b++) s += d_gpart[(size_t)b * (CC * CC) + i];
        d_gram[i] = s;
    } else {
        if (tid < CC) {
            float s = 0.f;
#pragma unroll 8
            for (int b = 0; b < GBLK; b++) s += d_cpart[b * CC + tid];
            d_chsum[tid] = s;
        }
        if (tid == 128) { d_trace = 0.f; g_bar = 0u; }
    }
}

// ---------------- kernel 3: Newton-Schulz, direct-L2, k-split x2 (R10 measured-best) ---
__device__ __forceinline__ void gsync(unsigned &tgt) {
    __threadfence();
    __syncthreads();
    tgt += NSB;
    if (threadIdx.x == 0) {
        atomicAdd(&g_bar, 1u);
        while (*(volatile unsigned*)&g_bar < tgt) {}
    }
    __syncthreads();
}
__device__ __forceinline__ float halfdot(const float* __restrict__ v,
                                         const float* __restrict__ M, int j) {
    float a0 = 0.f, a1 = 0.f, a2 = 0.f, a3 = 0.f;
#pragma unroll
    for (int k = 0; k < 64; k += 4) {
        float4 pv = *(const float4*)(v + k);
        a0 = fmaf(pv.x, __ldcg(&M[(k + 0) * CC + j]), a0);
        a1 = fmaf(pv.y, __ldcg(&M[(k + 1) * CC + j]), a1);
        a2 = fmaf(pv.z, __ldcg(&M[(k + 2) * CC + j]), a2);
        a3 = fmaf(pv.w, __ldcg(&M[(k + 3) * CC + j]), a3);
    }
    return (a0 + a1) + (a2 + a3);
}
__global__ void __launch_bounds__(256, 1) ns_kernel(const float* __restrict__ beta) {
    __shared__ float mean_s[CC], pr_s[CC], t1_s[CC], t2_s[CC];
    __shared__ float p1[2][CC], p2[2][CC], pu[2][CC];
    __shared__ float rtr_s;
    const int tid = threadIdx.x;
    const int j = tid & 127, h = tid >> 7;
    const int r = blockIdx.x;

    if (h == 0) mean_s[j] = d_chsum[j] * (1.f / (float)MTOT);
    __syncthreads();
    if (h == 0) {
        float sig = d_gram[r*CC + j] * (1.f / (float)MTOT) - mean_s[r] * mean_s[j]
                    + ((j == r) ? EPSI : 0.f);
        __stcg(&d_Sig[r*CC + j], sig);
        __stcg(&d_P2[0][r*CC + j], (j == r) ? 1.f : 0.f);
        if (j == r) atomicAdd(&d_trace, sig);
    }
    unsigned tgt = 0;
    gsync(tgt);
    if (tid == 0) rtr_s = 1.f / *(volatile float*)&d_trace;
    __syncthreads();
    const float rtr = rtr_s;

    int cur = 0;
    for (int it = 0; it < TITER; ++it) {
        const float* P = d_P2[cur];
        if (h == 0) pr_s[j] = __ldcg(&P[r*CC + j]);
        __syncthreads();
        p1[h][j] = halfdot(pr_s + h*64, P + (size_t)h*64*CC, j);
        __syncthreads();
        if (h == 0) t1_s[j] = p1[0][j] + p1[1][j];
        __syncthreads();
        p2[h][j] = halfdot(t1_s + h*64, P + (size_t)h*64*CC, j);
        __syncthreads();
        if (h == 0) t2_s[j] = p2[0][j] + p2[1][j];
        __syncthreads();
        pu[h][j] = halfdot(t2_s + h*64, d_Sig + (size_t)h*64*CC, j);
        __syncthreads();
        if (h == 0) {
            float u = pu[0][j] + pu[1][j];
            __stcg(&d_P2[1 - cur][r*CC + j], 1.5f * pr_s[j] - 0.5f * rtr * u);
        }
        gsync(tgt);
        cur ^= 1;
    }

    if (h == 0) {
        float w = __ldcg(&d_P2[cur][r*CC + j]) * sqrtf(rtr);
        d_wmf[r*CC + j] = w;
        t1_s[j] = w * mean_s[j];
    }
    __syncthreads();
    for (int s = 64; s > 0; s >>= 1) {
        if (tid < s) t1_s[tid] += t1_s[tid + s];
        __syncthreads();
    }
    if (tid == 0) d_bias2[r] = beta[r] - t1_s[0];
}

// ---------------- kernel 4: whitening, SINGLE-PASS tf32 (m16n8k8), 4 p-tiles ------
// wm[c][d] pitch 132 fl (A-frag banks 4c+d: conflict-free); X[d][p] pitch 72 fl
// (B-frag banks 8d+p: conflict-free). Register prefetch of next tile during MMA.
__global__ void __launch_bounds__(256) whit_kernel(const float* __restrict__ X,
                                                   float* __restrict__ Y) {
    extern __shared__ char sm[];
    const int tid = threadIdx.x, wid = tid >> 5, lane = tid & 31;

    {   // stage wm -> tf32 smem, once per CTA
        const float4* wf = (const float4*)d_wmf;
        unsigned* wsm = (unsigned*)sm;
#pragma unroll 4
        for (int i = tid; i < 4096; i += 256) {
            int c = i >> 5, dg = (i & 31) * 4;
            float4 v = wf[i];
            *(uint4*)(wsm + c * WP + dg) =
                make_uint4(cvt_tf32(v.x), cvt_tf32(v.y), cvt_tf32(v.z), cvt_tf32(v.w));
        }
    }
    if (tid < 128) ((float*)(sm + S_BIAS))[tid] = d_bias2[tid];

    const float* Wp = (const float*)sm;
    const float* Xp = (const float*)(sm + S_X);
    unsigned* Xw = (unsigned*)(sm + S_X);
    const int arow = wid * 16 + (lane >> 2);
    const int ad = lane & 3;
    const int bp = lane >> 2;
    const int cr = tid >> 2, cq = tid & 3;

    // prefetch tile 0
    float4 pf[8];
    {
        const int g0 = blockIdx.x * 4;
        const int n0 = g0 / 49, pp0 = (g0 % 49) * 64;
#pragma unroll
        for (int hh = 0; hh < 2; ++hh) {
            const float* xp = X + ((size_t)n0 * CC + cr + hh * 64) * HWP + pp0 + cq * 16;
#pragma unroll
            for (int i = 0; i < 4; ++i) pf[hh * 4 + i] = *(const float4*)(xp + 4 * i);
        }
    }

    for (int t = 0; t < 4; ++t) {
        const int g = blockIdx.x * 4 + t;
        const int n = g / 49, p0 = (g % 49) * 64;
        if (t) __syncthreads();
        {   // convert prefetched regs -> tf32 smem
#pragma unroll
            for (int hh = 0; hh < 2; ++hh) {
                const int row = cr + hh * 64;
                unsigned* dst = Xw + row * XP + cq * 16;
#pragma unroll
                for (int i = 0; i < 4; ++i) {
                    float4 v = pf[hh * 4 + i];
                    *(uint4*)(dst + 4 * i) =
                        make_uint4(cvt_tf32(v.x), cvt_tf32(v.y), cvt_tf32(v.z), cvt_tf32(v.w));
                }
            }
        }
        __syncthreads();

        if (t < 3) {   // prefetch tile t+1 (lands during MMA)
            const int g2 = blockIdx.x * 4 + t + 1;
            const int n2 = g2 / 49, pp2 = (g2 % 49) * 64;
#pragma unroll
            for (int hh = 0; hh < 2; ++hh) {
                const float* xp = X + ((size_t)n2 * CC + cr + hh * 64) * HWP + pp2 + cq * 16;
#pragma unroll
                for (int i = 0; i < 4; ++i) pf[hh * 4 + i] = *(const float4*)(xp + 4 * i);
            }
        }

        float acc[8][4];
#pragma unroll
        for (int jj = 0; jj < 8; ++jj)
#pragma unroll
            for (int z = 0; z < 4; ++z) acc[jj][z] = 0.f;

#pragma unroll
        for (int kt = 0; kt < 16; ++kt) {
            const int k0 = kt * 8;
            unsigned a0 = __float_as_uint(Wp[arow * WP + k0 + ad]);
            unsigned a1 = __float_as_uint(Wp[(arow + 8) * WP + k0 + ad]);
            unsigned a2 = __float_as_uint(Wp[arow * WP + k0 + ad + 4]);
            unsigned a3 = __float_as_uint(Wp[(arow + 8) * WP + k0 + ad + 4]);
            const float* xb0 = Xp + (k0 + ad) * XP + bp;
            const float* xb1 = Xp + (k0 + ad + 4) * XP + bp;
#pragma unroll
            for (int jj = 0; jj < 8; ++jj) {
                unsigned b0 = __float_as_uint(xb0[jj * 8]);
                unsigned b1 = __float_as_uint(xb1[jj * 8]);
                mma_tf32(acc[jj], a0, a1, a2, a3, b0, b1);
            }
        }

        const int row0 = wid * 16 + (lane >> 2);
        const float b0 = ((const float*)(sm + S_BIAS))[row0];
        const float b1 = ((const float*)(sm + S_BIAS))[row0 + 8];
        float* y0 = Y + ((size_t)n * CC + row0) * HWP + p0 + (lane & 3) * 2;
#pragma unroll
        for (int jj = 0; jj < 8; ++jj) {
            *(float2*)(y0 + 8 * jj)           = make_float2(acc[jj][0] + b0, acc[jj][1] + b0);
            *(float2*)(y0 + 8 * jj + 8 * HWP) = make_float2(acc[jj][2] + b1, acc[jj][3] + b1);
        }
    }
}

// ---------------- launch ----------------
extern "C" void kernel_launch(void* const* d_in, const int* in_sizes, int n_in,
                              void* d_out, int out_size) {
    const float* X = (const float*)d_in[0];
    const float* beta = (const float*)d_in[1];
    float* Y = (float*)d_out;
    cudaFuncSetAttribute(whit_kernel, cudaFuncAttributeMaxDynamicSharedMemorySize, WHIT_SMEM);
    gram_kernel<<<GBLK, 256>>>(X);
    reduce_kernel<<<65, 256>>>();
    ns_kernel<<<NSB, 256>>>(beta);
    whit_kernel<<<784, 256, WHIT_SMEM>>>(X, Y);
}

// round 14
// speedup vs baseline: 1.2063x; 1.1041x over previous
#include <cuda_runtime.h>
#include <cuda_bf16.h>

#define NN    64
#define CC    128
#define HWP   3136
#define MTOT  200704
#define EPSI  1e-5f
#define TITER 10
#define NSB   128
#define GCHUNK 784
#define GBLK  256

// gram smem: [buf 0/1][128 rows][48B] (hi only, 1-pass)
#define PITCHB 48
#define GBUF   (128 * PITCHB)

// whit smem: wm [c=128][d, pitch 132 fl] tf32 ; X [p=64][d, pitch 132 fl] tf32
#define WP 132
#define XP2 132
#define S_X    (128 * WP * 4)            // 67584
#define S_BIAS (S_X + 64 * XP2 * 4)      // 101376
#define WHIT_SMEM (S_BIAS + 512)         // 101888

// ---------------- scratch ----------------
__device__ float d_gpart[GBLK * CC * CC];
__device__ float d_cpart[GBLK * CC];
__device__ float d_gram[CC * CC];
__device__ float d_chsum[CC];
__device__ float d_Sig[CC * CC];
__device__ float d_P2[2][CC * CC];
__device__ float d_wmf[CC * CC];
__device__ float d_bias2[CC];
__device__ float d_trace;
__device__ unsigned g_bar;

// ---------------- helpers ----------------
__device__ __forceinline__ unsigned smem_u32(const void* p) {
    unsigned r; asm("{ .reg .u64 t; cvta.to.shared.u64 t, %1; cvt.u32.u64 %0, t; }" : "=r"(r) : "l"(p)); return r;
}
__device__ __forceinline__ void ldsm_x4(unsigned &r0, unsigned &r1, unsigned &r2, unsigned &r3, unsigned a) {
    asm volatile("ldmatrix.sync.aligned.m8n8.x4.shared.b16 {%0,%1,%2,%3}, [%4];"
                 : "=r"(r0), "=r"(r1), "=r"(r2), "=r"(r3) : "r"(a));
}
__device__ __forceinline__ void mma_bf16(float* d, unsigned a0, unsigned a1, unsigned a2, unsigned a3,
                                         unsigned b0, unsigned b1) {
    asm volatile("mma.sync.aligned.m16n8k16.row.col.f32.bf16.bf16.f32 "
                 "{%0,%1,%2,%3}, {%4,%5,%6,%7}, {%8,%9}, {%0,%1,%2,%3};"
                 : "+f"(d[0]), "+f"(d[1]), "+f"(d[2]), "+f"(d[3])
                 : "r"(a0), "r"(a1), "r"(a2), "r"(a3), "r"(b0), "r"(b1));
}
__device__ __forceinline__ void mma_tf32(float* d, unsigned a0, unsigned a1, unsigned a2, unsigned a3,
                                         unsigned b0, unsigned b1) {
    asm volatile("mma.sync.aligned.m16n8k8.row.col.f32.tf32.tf32.f32 "
                 "{%0,%1,%2,%3}, {%4,%5,%6,%7}, {%8,%9}, {%0,%1,%2,%3};"
                 : "+f"(d[0]), "+f"(d[1]), "+f"(d[2]), "+f"(d[3])
                 : "r"(a0), "r"(a1), "r"(a2), "r"(a3), "r"(b0), "r"(b1));
}
__device__ __forceinline__ unsigned pkbf(float a, float b) {
    __nv_bfloat162 t(__float2bfloat16(a), __float2bfloat16(b));
    return *(unsigned*)&t;
}
__device__ __forceinline__ unsigned cvt_tf32(float f) {
    unsigned r; asm("cvt.rna.tf32.f32 %0, %1;" : "=r"(r) : "f"(f)); return r;
}

// ---------------- kernel 1: Gram via mma.sync, 1-pass bf16 (measured-good) ----
__global__ void __launch_bounds__(256, 2) gram_kernel(const float* __restrict__ X) {
    __shared__ __align__(16) char sm[2 * GBUF];
    __shared__ float chs[CC];
    const int tid = threadIdx.x, wid = tid >> 5, lane = tid & 31;
    const unsigned smb = smem_u32(sm);
    const int n = blockIdx.x >> 2;
    const int pbase = (blockIdx.x & 3) * GCHUNK;
    const float* Xn = X + (size_t)n * (CC * HWP) + pbase;

    const int r = tid >> 1, q = tid & 1;
    const float* gsrc = Xn + (size_t)r * HWP + q * 8;
    if (tid < CC) chs[tid] = 0.f;

    float acc[16][4];
#pragma unroll
    for (int j = 0; j < 16; ++j)
#pragma unroll
        for (int z = 0; z < 4; ++z) acc[j][z] = 0.f;
    float cs = 0.f;

    const unsigned a_off = (unsigned)((wid * 16 + (lane & 15)) * PITCHB + (lane >> 4) * 16);
    const unsigned b_row = (unsigned)((lane >> 4) * 8 + (lane & 7));
    const unsigned b_koff = (unsigned)(((lane >> 3) & 1) * 16);
    const unsigned st_off = (unsigned)(r * PITCHB + q * 16);

    float4 pv0 = *(const float4*)(gsrc);
    float4 pv1 = *(const float4*)(gsrc + 4);

    for (int t = 0; t < 49; ++t) {
        char* base = sm + (t & 1) * GBUF;
        {
            unsigned h0 = pkbf(pv0.x, pv0.y), h1 = pkbf(pv0.z, pv0.w);
            unsigned h2 = pkbf(pv1.x, pv1.y), h3 = pkbf(pv1.z, pv1.w);
            *(uint4*)(base + st_off) = make_uint4(h0, h1, h2, h3);
            cs += ((pv0.x + pv0.y) + (pv0.z + pv0.w)) + ((pv1.x + pv1.y) + (pv1.z + pv1.w));
        }
        __syncthreads();
        if (t < 48) {
            pv0 = *(const float4*)(gsrc + (t + 1) * 16);
            pv1 = *(const float4*)(gsrc + (t + 1) * 16 + 4);
        }
        const unsigned tb = smb + (unsigned)((t & 1) * GBUF);
        unsigned ah0, ah1, ah2, ah3;
        ldsm_x4(ah0, ah1, ah2, ah3, tb + a_off);
#pragma unroll
        for (int p = 0; p < 8; ++p) {
            const unsigned ba = tb + (unsigned)((16 * p + b_row) * PITCHB) + b_koff;
            unsigned bh0, bh1, bh2, bh3;
            ldsm_x4(bh0, bh1, bh2, bh3, ba);
            mma_bf16(acc[2*p],   ah0, ah1, ah2, ah3, bh0, bh1);
            mma_bf16(acc[2*p+1], ah0, ah1, ah2, ah3, bh2, bh3);
        }
    }

    __syncthreads();
    atomicAdd(&chs[r], cs);
    __syncthreads();
    if (tid < CC) d_cpart[blockIdx.x * CC + tid] = chs[tid];

    float* gp = d_gpart + (size_t)blockIdx.x * (CC * CC);
    const int row0 = wid * 16 + (lane >> 2);
#pragma unroll
    for (int j = 0; j < 16; ++j) {
        const int col = j * 8 + (lane & 3) * 2;
        *(float2*)(gp + row0 * CC + col)       = make_float2(acc[j][0], acc[j][1]);
        *(float2*)(gp + (row0 + 8) * CC + col) = make_float2(acc[j][2], acc[j][3]);
    }
}

// ---------------- kernel 2: reduce + zero barrier/trace ----------------
__global__ void reduce_kernel() {
    const int bid = blockIdx.x, tid = threadIdx.x;
    if (bid < 64) {
        const int i = bid * 256 + tid;
        float s = 0.f;
#pragma unroll 8
        for (int b = 0; b < GBLK; b++) s += d_gpart[(size_t)b * (CC * CC) + i];
        d_gram[i] = s;
    } else {
        if (tid < CC) {
            float s = 0.f;
#pragma unroll 8
            for (int b = 0; b < GBLK; b++) s += d_cpart[b * CC + tid];
            d_chsum[tid] = s;
        }
        if (tid == 128) { d_trace = 0.f; g_bar = 0u; }
    }
}

// ---------------- kernel 3: Newton-Schulz (R10 measured-best) ----------------
__device__ __forceinline__ void gsync(unsigned &tgt) {
    __threadfence();
    __syncthreads();
    tgt += NSB;
    if (threadIdx.x == 0) {
        atomicAdd(&g_bar, 1u);
        while (*(volatile unsigned*)&g_bar < tgt) {}
    }
    __syncthreads();
}
__device__ __forceinline__ float halfdot(const float* __restrict__ v,
                                         const float* __restrict__ M, int j) {
    float a0 = 0.f, a1 = 0.f, a2 = 0.f, a3 = 0.f;
#pragma unroll
    for (int k = 0; k < 64; k += 4) {
        float4 pv = *(const float4*)(v + k);
        a0 = fmaf(pv.x, __ldcg(&M[(k + 0) * CC + j]), a0);
        a1 = fmaf(pv.y, __ldcg(&M[(k + 1) * CC + j]), a1);
        a2 = fmaf(pv.z, __ldcg(&M[(k + 2) * CC + j]), a2);
        a3 = fmaf(pv.w, __ldcg(&M[(k + 3) * CC + j]), a3);
    }
    return (a0 + a1) + (a2 + a3);
}
__global__ void __launch_bounds__(256, 1) ns_kernel(const float* __restrict__ beta) {
    __shared__ float mean_s[CC], pr_s[CC], t1_s[CC], t2_s[CC];
    __shared__ float p1[2][CC], p2[2][CC], pu[2][CC];
    __shared__ float rtr_s;
    const int tid = threadIdx.x;
    const int j = tid & 127, h = tid >> 7;
    const int r = blockIdx.x;

    if (h == 0) mean_s[j] = d_chsum[j] * (1.f / (float)MTOT);
    __syncthreads();
    if (h == 0) {
        float sig = d_gram[r*CC + j] * (1.f / (float)MTOT) - mean_s[r] * mean_s[j]
                    + ((j == r) ? EPSI : 0.f);
        __stcg(&d_Sig[r*CC + j], sig);
        __stcg(&d_P2[0][r*CC + j], (j == r) ? 1.f : 0.f);
        if (j == r) atomicAdd(&d_trace, sig);
    }
    unsigned tgt = 0;
    gsync(tgt);
    if (tid == 0) rtr_s = 1.f / *(volatile float*)&d_trace;
    __syncthreads();
    const float rtr = rtr_s;

    int cur = 0;
    for (int it = 0; it < TITER; ++it) {
        const float* P = d_P2[cur];
        if (h == 0) pr_s[j] = __ldcg(&P[r*CC + j]);
        __syncthreads();
        p1[h][j] = halfdot(pr_s + h*64, P + (size_t)h*64*CC, j);
        __syncthreads();
        if (h == 0) t1_s[j] = p1[0][j] + p1[1][j];
        __syncthreads();
        p2[h][j] = halfdot(t1_s + h*64, P + (size_t)h*64*CC, j);
        __syncthreads();
        if (h == 0) t2_s[j] = p2[0][j] + p2[1][j];
        __syncthreads();
        pu[h][j] = halfdot(t2_s + h*64, d_Sig + (size_t)h*64*CC, j);
        __syncthreads();
        if (h == 0) {
            float u = pu[0][j] + pu[1][j];
            __stcg(&d_P2[1 - cur][r*CC + j], 1.5f * pr_s[j] - 0.5f * rtr * u);
        }
        gsync(tgt);
        cur ^= 1;
    }

    if (h == 0) {
        float w = __ldcg(&d_P2[cur][r*CC + j]) * sqrtf(rtr);
        d_wmf[r*CC + j] = w;
        t1_s[j] = w * mean_s[j];
    }
    __syncthreads();
    for (int s = 64; s > 0; s >>= 1) {
        if (tid < s) t1_s[tid] += t1_s[tid + s];
        __syncthreads();
    }
    if (tid == 0) d_bias2[r] = beta[r] - t1_s[0];
}

// ---------------- kernel 4: whitening, tf32 + ldmatrix frags, X transposed [p][d] ----
__global__ void __launch_bounds__(256) whit_kernel(const float* __restrict__ X,
                                                   float* __restrict__ Y) {
    extern __shared__ char sm[];
    const int tid = threadIdx.x, wid = tid >> 5, lane = tid & 31;
    const unsigned smb = smem_u32(sm);

    {   // stage wm -> tf32 smem [c][d] pitch WP, once per CTA
        const float4* wf = (const float4*)d_wmf;
        unsigned* wsm = (unsigned*)sm;
#pragma unroll 4
        for (int i = tid; i < 4096; i += 256) {
            int c = i >> 5, dg = (i & 31) * 4;
            float4 v = wf[i];
            *(uint4*)(wsm + c * WP + dg) =
                make_uint4(cvt_tf32(v.x), cvt_tf32(v.y), cvt_tf32(v.z), cvt_tf32(v.w));
        }
    }
    if (tid < 128) ((float*)(sm + S_BIAS))[tid] = d_bias2[tid];

    // ldmatrix lane addressing (bytes)
    const unsigned a_base = smb
        + (unsigned)((wid * 16 + (lane & 7) + ((lane >> 3) & 1) * 8) * WP * 4)
        + (unsigned)((lane >> 4) * 16);
    unsigned b_base[4];
#pragma unroll
    for (int qq = 0; qq < 4; ++qq)
        b_base[qq] = smb + S_X
            + (unsigned)((qq * 16 + (lane & 7) + (lane >> 4) * 8) * XP2 * 4)
            + (unsigned)(((lane >> 3) & 1) * 16);

    // conversion mapping: thread owns column-slice (p fixed, 32 d's)
    const int cp = tid & 63;             // pixel 0..63
    const int cd0 = (tid >> 6) * 32;     // d range start
    unsigned* Xw = (unsigned*)(sm + S_X);

    // prefetch tile 0 (32 scalars, warp-coalesced along p)
    float pf[32];
    {
        const int g0 = blockIdx.x * 4;
        const int n0 = g0 / 49, pp0 = (g0 % 49) * 64;
        const float* xp = X + ((size_t)n0 * CC + cd0) * HWP + pp0 + cp;
#pragma unroll
        for (int i = 0; i < 32; ++i) pf[i] = __ldg(xp + (size_t)i * HWP);
    }

    for (int t = 0; t < 4; ++t) {
        const int g = blockIdx.x * 4 + t;
        const int n = g / 49, p0 = (g % 49) * 64;
        if (t) __syncthreads();
        {   // convert prefetched regs -> tf32 smem [p][d]
            unsigned* dst = Xw + cp * XP2 + cd0;
#pragma unroll
            for (int i = 0; i < 8; ++i)
                *(uint4*)(dst + 4 * i) = make_uint4(cvt_tf32(pf[4*i]), cvt_tf32(pf[4*i+1]),
                                                    cvt_tf32(pf[4*i+2]), cvt_tf32(pf[4*i+3]));
        }
        __syncthreads();

        if (t < 3) {   // prefetch tile t+1 (lands during MMA)
            const int g2 = blockIdx.x * 4 + t + 1;
            const int n2 = g2 / 49, pp2 = (g2 % 49) * 64;
            const float* xp = X + ((size_t)n2 * CC + cd0) * HWP + pp2 + cp;
#pragma unroll
            for (int i = 0; i < 32; ++i) pf[i] = __ldg(xp + (size_t)i * HWP);
        }

        float acc[8][4];
#pragma unroll
        for (int jj = 0; jj < 8; ++jj)
#pragma unroll
            for (int z = 0; z < 4; ++z) acc[jj][z] = 0.f;

#pragma unroll
        for (int kt = 0; kt < 16; ++kt) {
            const unsigned ko = (unsigned)(kt * 32);
            unsigned a0, a1, a2, a3;
            ldsm_x4(a0, a1, a2, a3, a_base + ko);
#pragma unroll
            for (int qq = 0; qq < 4; ++qq) {
                unsigned b0, b1, b2, b3;
                ldsm_x4(b0, b1, b2, b3, b_base[qq] + ko);
                mma_tf32(acc[2*qq],   a0, a1, a2, a3, b0, b1);
                mma_tf32(acc[2*qq+1], a0, a1, a2, a3, b2, b3);
            }
        }

        const int row0 = wid * 16 + (lane >> 2);
        const float b0 = ((const float*)(sm + S_BIAS))[row0];
        const float b1 = ((const float*)(sm + S_BIAS))[row0 + 8];
        float* y0 = Y + ((size_t)n * CC + row0) * HWP + p0 + (lane & 3) * 2;
#pragma unroll
        for (int jj = 0; jj < 8; ++jj) {
            *(float2*)(y0 + 8 * jj)           = make_float2(acc[jj][0] + b0, acc[jj][1] + b0);
            *(float2*)(y0 + 8 * jj + 8 * HWP) = make_float2(acc[jj][2] + b1, acc[jj][3] + b1);
        }
    }
}

// ---------------- launch ----------------
extern "C" void kernel_launch(void* const* d_in, const int* in_sizes, int n_in,
                              void* d_out, int out_size) {
    const float* X = (const float*)d_in[0];
    const float* beta = (const float*)d_in[1];
    float* Y = (float*)d_out;
    cudaFuncSetAttribute(whit_kernel, cudaFuncAttributeMaxDynamicSharedMemorySize, WHIT_SMEM);
    gram_kernel<<<GBLK, 256>>>(X);
    reduce_kernel<<<65, 256>>>();
    ns_kernel<<<NSB, 256>>>(beta);
    whit_kernel<<<784, 256, WHIT_SMEM>>>(X, Y);
}